// round 11
// baseline (speedup 1.0000x reference)
#include <cuda_runtime.h>
#include <cuda_fp16.h>
#include <cstdint>

#define NT 256
#define BM 64

// fp16 fragment-packed weights, written by prepack:
// [0,32768)     hW2 frags, uint4-paired: ((kk*16+np)*32+lane)*4 + wd,
//               wd: nt=2np+(wd>>1), br=wd&1
// [32768,65536) fW2 frags (same layout)
// [65536,67584) fW3 frags: ((kk*2+nf)*32+lane)*2+br
// [67584,69632) hW1 frags: (nf*32+lane)*2+br   (K=16, single kk)
// [69632,71680) fW1 frags
__device__ __align__(16) uint32_t g_wpk[71680];

// ---- smem byte offsets ----
#define O_SA   0u        // 32KB: t1 frags -> h frags (canonical A-frag layout)
#define O_SB   32768u    // 32KB: f frags -> g frags
#define O_RING 65536u    // 4 x 8KB cp.async ring
#define O_HB1  98304u    // f32[256]
#define O_FB1  99328u
#define O_HB2  100352u
#define O_FB2  101376u
#define O_FB3  102400u   // f32[16]
#define SMEMB  102464

#define CP_ASYNC16(d, s) \
    asm volatile("cp.async.cg.shared.global [%0], [%1], 16;" :: "r"(d), "l"(s))
#define CP_COMMIT() asm volatile("cp.async.commit_group;" ::: "memory")
#define CP_WAIT2()  asm volatile("cp.async.wait_group 2;" ::: "memory")
// pair barrier: the 64 threads (2 warps) that both stage and read one B quarter
#define PAIR_BAR(id) asm volatile("bar.sync %0, 64;" :: "r"(id) : "memory")

__device__ __forceinline__ uint32_t smem_u32(const void* p) {
    uint32_t a;
    asm("{ .reg .u64 t; cvta.to.shared.u64 t, %1; cvt.u32.u64 %0, t; }" : "=r"(a) : "l"(p));
    return a;
}
// hardware tanh: 1 MUFU op
__device__ __forceinline__ float fast_tanh(float x) {
    float y;
    asm("tanh.approx.f32 %0, %1;" : "=f"(y) : "f"(x));
    return y;
}
__device__ __forceinline__ uint32_t h2u(float lo, float hi) {
    uint32_t r;
    asm("{ .reg .b16 l, h; cvt.rn.f16.f32 l, %1; cvt.rn.f16.f32 h, %2; mov.b32 %0, {l, h}; }"
        : "=r"(r) : "f"(lo), "f"(hi));
    return r;
}
__device__ __forceinline__ float2 uh2(uint32_t u) {
    __half2 h = *(__half2*)&u;
    return __half22float2(h);
}
__device__ __forceinline__ void mma16816(float d[4],
    uint32_t a0, uint32_t a1, uint32_t a2, uint32_t a3, uint32_t b0, uint32_t b1) {
    asm volatile("mma.sync.aligned.m16n8k16.row.col.f32.f16.f16.f32 "
                 "{%0,%1,%2,%3},{%4,%5,%6,%7},{%8,%9},{%0,%1,%2,%3};"
                 : "+f"(d[0]), "+f"(d[1]), "+f"(d[2]), "+f"(d[3])
                 : "r"(a0), "r"(a1), "r"(a2), "r"(a3), "r"(b0), "r"(b1));
}

// ---------- prepack ----------
__global__ void __launch_bounds__(512) prepack(const float* __restrict__ hW2,
                                               const float* __restrict__ fW2,
                                               const float* __restrict__ fW3,
                                               const float* __restrict__ hW1,
                                               const float* __restrict__ fW1) {
    int tid = blockIdx.x * 512 + threadIdx.x;
    if (tid < 65536) {
        int off = tid & 32767;
        const float* W = (tid >> 15) ? fW2 : hW2;
        // uint4-paired layout: wd selects (nt parity, br)
        int wd = off & 3, lane = (off >> 2) & 31, np = (off >> 7) & 15, kk = off >> 11;
        int nt = 2 * np + (wd >> 1), br = wd & 1;
        int n = nt * 8 + (lane >> 2), k = kk * 16 + 2 * (lane & 3) + br * 8;
        g_wpk[tid] = h2u(W[n * 256 + k], W[n * 256 + k + 1]);
    } else if (tid < 67584) {
        int off = tid - 65536;
        int br = off & 1, lane = (off >> 1) & 31, nf = (off >> 6) & 1, kk = off >> 7;
        int n = nf * 8 + (lane >> 2), k = kk * 16 + 2 * (lane & 3) + br * 8;
        g_wpk[tid] = h2u(fW3[n * 256 + k], fW3[n * 256 + k + 1]);
    } else if (tid < 71680) {
        int off = tid - 67584;
        const float* W = (off >= 2048) ? fW1 : hW1;
        off &= 2047;
        int br = off & 1, lane = (off >> 1) & 31, nf = off >> 6;
        int n = nf * 8 + (lane >> 2), k = 2 * (lane & 3) + br * 8;
        g_wpk[tid] = h2u(W[n * 16 + k], W[n * 16 + k + 1]);
    }
}

__device__ __forceinline__ void ring_issue(uint32_t ringb, const uint32_t* wsrc, int c, int t) {
    if (c < 16) {
        uint32_t dst = ringb + (uint32_t)(((c & 3) << 13) + (t << 5));
        const char* src = (const char*)(wsrc + (c << 11)) + (t << 5);
        CP_ASYNC16(dst, src);
        CP_ASYNC16(dst + 16, src + 16);
    }
    CP_COMMIT();
}

#define ZERO_ACC(acc) do { \
    _Pragma("unroll") for (int _m = 0; _m < 2; ++_m) \
    _Pragma("unroll") for (int _n = 0; _n < 8; ++_n) \
    _Pragma("unroll") for (int _i = 0; _i < 4; ++_i) (acc)[_m][_n][_i] = 0.0f; \
} while (0)

// Big GEMM: A frags from ab (smem), B streamed from wsrc via ring.
// Mainloop uses PAIR barriers only; A is register double-buffered (A(kk+1)
// loaded during kk's MMAs — SA/SB are stable for the whole gemm), and the
// cp.async issue rides in the B-LDS latency shadow.
// Prologue (chunks 0..2) must already be issued. Ends with a pair barrier.
__device__ __forceinline__ void gemm_ring(const uint4* __restrict__ ab, const char* smx,
                                          uint32_t ringb, const uint32_t* __restrict__ wsrc,
                                          int wrow, int wcol, int lane, int t,
                                          float acc[2][8][4]) {
    const int s0 = wrow * 2;
    const int bid = 1 + wcol;
    uint4 A0 = ab[(s0 * 16) * 32 + lane];          // preload kk=0 (post caller-sync)
    uint4 A1 = ab[((s0 + 1) * 16) * 32 + lane];
#pragma unroll
    for (int kk = 0; kk < 16; ++kk) {
        CP_WAIT2();
        PAIR_BAR(bid);
        const uint4* rb4 = (const uint4*)(smx + O_RING + ((kk & 3) << 13));
        uint4 B[4];
#pragma unroll
        for (int j = 0; j < 4; ++j)
            B[j] = rb4[((wcol << 2) + j) * 32 + lane];
        ring_issue(ringb, wsrc, kk + 3, t);        // in B-LDS shadow
        uint4 C0 = A0, C1 = A1;
        if (kk < 15) {                             // prefetch next-kk A during MMAs
            A0 = ab[(s0 * 16 + kk + 1) * 32 + lane];
            A1 = ab[((s0 + 1) * 16 + kk + 1) * 32 + lane];
        }
#pragma unroll
        for (int j = 0; j < 4; ++j) {
            mma16816(acc[0][2*j],   C0.x, C0.y, C0.z, C0.w, B[j].x, B[j].y);
            mma16816(acc[1][2*j],   C1.x, C1.y, C1.z, C1.w, B[j].x, B[j].y);
            mma16816(acc[0][2*j+1], C0.x, C0.y, C0.z, C0.w, B[j].z, B[j].w);
            mma16816(acc[1][2*j+1], C1.x, C1.y, C1.z, C1.w, B[j].z, B[j].w);
        }
    }
    PAIR_BAR(bid);   // pair's ring reads done before slots reused by next prologue
}

__global__ void __launch_bounds__(NT, 2)
flexhnn_f16(const float* __restrict__ z,
            const float* __restrict__ hb1, const float* __restrict__ hb2,
            const float* __restrict__ fb1, const float* __restrict__ fb2,
            const float* __restrict__ fb3,
            float* __restrict__ out)
{
    extern __shared__ __align__(16) char smx[];
    float* smF = (float*)smx;
    uint4* sa4 = (uint4*)(smx + O_SA);
    uint4* sb4 = (uint4*)(smx + O_SB);
    const uint32_t ringb = smem_u32(smx) + O_RING;

    const int t = threadIdx.x, lane = t & 31, w = t >> 5;
    const int fr = lane >> 2, fc = lane & 3;
    const int wrow = w & 1, wcol = w >> 1;     // 8 warps: 2 row-halves x 4 col-quarters
    const long n0 = (long)blockIdx.x * BM;

    // ---- early prefetch: GEMM1a B frags (hW1) — hides L2 latency behind staging ----
    uint2 B1[8];
#pragma unroll
    for (int nt = 0; nt < 8; ++nt)
        B1[nt] = *(const uint2*)(g_wpk + 67584 + (((wcol << 3) + nt) * 32 + lane) * 2);

    // ---- GEMM1: z A-frags (fp16) ----
    uint4 Az[2];
#pragma unroll
    for (int mt = 0; mt < 2; ++mt) {
        const long rl = n0 + (wrow * 32 + mt * 16 + fr);
        float2 zl0 = *(const float2*)(z + rl * 16 + 2 * fc);
        float2 zl8 = *(const float2*)(z + rl * 16 + 2 * fc + 8);
        float2 zh0 = *(const float2*)(z + (rl + 8) * 16 + 2 * fc);
        float2 zh8 = *(const float2*)(z + (rl + 8) * 16 + 2 * fc + 8);
        Az[mt].x = h2u(zl0.x, zl0.y); Az[mt].y = h2u(zh0.x, zh0.y);
        Az[mt].z = h2u(zl8.x, zl8.y); Az[mt].w = h2u(zh8.x, zh8.y);
    }

    // ---- stage biases ----
    smF[O_HB1 / 4 + t] = hb1[t];
    smF[O_FB1 / 4 + t] = fb1[t];
    smF[O_HB2 / 4 + t] = hb2[t];
    smF[O_FB2 / 4 + t] = fb2[t];
    if (t < 16) smF[O_FB3 / 4 + t] = fb3[t];
    __syncthreads();

    float acc[2][8][4];

    // ---- GEMM1a: a1 = z @ hW1^T ; epi1a: t1 -> SA frags ----
    ZERO_ACC(acc);
#pragma unroll
    for (int nt = 0; nt < 8; ++nt) {
        mma16816(acc[0][nt], Az[0].x, Az[0].y, Az[0].z, Az[0].w, B1[nt].x, B1[nt].y);
        mma16816(acc[1][nt], Az[1].x, Az[1].y, Az[1].z, Az[1].w, B1[nt].x, B1[nt].y);
    }
    // prefetch GEMM1b B frags (fW1) during epi1a
#pragma unroll
    for (int nt = 0; nt < 8; ++nt)
        B1[nt] = *(const uint2*)(g_wpk + 69632 + (((wcol << 3) + nt) * 32 + lane) * 2);
#pragma unroll
    for (int mt = 0; mt < 2; ++mt) {
        const int strip = wrow * 2 + mt;
#pragma unroll
        for (int j = 0; j < 4; ++j) {
            const int kkc = wcol * 4 + j;
            const int c0 = (wcol << 6) + (j << 4) + 2 * fc;
            float2 bA = *(const float2*)(smF + O_HB1 / 4 + c0);
            float2 bB = *(const float2*)(smF + O_HB1 / 4 + c0 + 8);
            uint4 v;
            v.x = h2u(fast_tanh(acc[mt][2*j][0] + bA.x), fast_tanh(acc[mt][2*j][1] + bA.y));
            v.y = h2u(fast_tanh(acc[mt][2*j][2] + bA.x), fast_tanh(acc[mt][2*j][3] + bA.y));
            v.z = h2u(fast_tanh(acc[mt][2*j+1][0] + bB.x), fast_tanh(acc[mt][2*j+1][1] + bB.y));
            v.w = h2u(fast_tanh(acc[mt][2*j+1][2] + bB.x), fast_tanh(acc[mt][2*j+1][3] + bB.y));
            sa4[(strip * 16 + kkc) * 32 + lane] = v;
        }
    }

    // ---- GEMM1b: f = z @ fW1^T + fb1 ; epi1b: f -> SB frags ----
    ZERO_ACC(acc);
#pragma unroll
    for (int nt = 0; nt < 8; ++nt) {
        mma16816(acc[0][nt], Az[0].x, Az[0].y, Az[0].z, Az[0].w, B1[nt].x, B1[nt].y);
        mma16816(acc[1][nt], Az[1].x, Az[1].y, Az[1].z, Az[1].w, B1[nt].x, B1[nt].y);
    }
#pragma unroll
    for (int mt = 0; mt < 2; ++mt) {
        const int strip = wrow * 2 + mt;
#pragma unroll
        for (int j = 0; j < 4; ++j) {
            const int kkc = wcol * 4 + j;
            const int c0 = (wcol << 6) + (j << 4) + 2 * fc;
            float2 bA = *(const float2*)(smF + O_FB1 / 4 + c0);
            float2 bB = *(const float2*)(smF + O_FB1 / 4 + c0 + 8);
            uint4 v;
            v.x = h2u(acc[mt][2*j][0] + bA.x, acc[mt][2*j][1] + bA.y);
            v.y = h2u(acc[mt][2*j][2] + bA.x, acc[mt][2*j][3] + bA.y);
            v.z = h2u(acc[mt][2*j+1][0] + bB.x, acc[mt][2*j+1][1] + bB.y);
            v.w = h2u(acc[mt][2*j+1][2] + bB.x, acc[mt][2*j+1][3] + bB.y);
            sb4[(strip * 16 + kkc) * 32 + lane] = v;
        }
    }

    // prologue for GEMM2 ring (hW2), then make SA/SB visible
    ring_issue(ringb, g_wpk, 0, t);
    ring_issue(ringb, g_wpk, 1, t);
    ring_issue(ringb, g_wpk, 2, t);
    __syncthreads();

    // ---- GEMM2: a2 = t1 @ hW2^T ----
    ZERO_ACC(acc);
    gemm_ring(sa4, smx, ringb, g_wpk, wrow, wcol, lane, t, acc);

    // prologue for GEMM3 ring (fW2) — overlaps epi2 (pair-local slot reuse is safe)
    ring_issue(ringb, g_wpk + 32768, 0, t);
    ring_issue(ringb, g_wpk + 32768, 1, t);
    ring_issue(ringb, g_wpk + 32768, 2, t);

    // ---- epi2: g = .5*f*s2 + .5*tanh(f)  (f from SB, overwrite with g) ----
#pragma unroll
    for (int mt = 0; mt < 2; ++mt) {
        const int strip = wrow * 2 + mt;
#pragma unroll
        for (int j = 0; j < 4; ++j) {
            const int kkc = wcol * 4 + j;
            const int c0 = (wcol << 6) + (j << 4) + 2 * fc;
            uint4* p = sb4 + (strip * 16 + kkc) * 32 + lane;
            uint4 fv = *p;
            float2 bA = *(const float2*)(smF + O_HB2 / 4 + c0);
            float2 bB = *(const float2*)(smF + O_HB2 / 4 + c0 + 8);
            float2 flo = uh2(fv.x), fhi = uh2(fv.y), glo = uh2(fv.z), ghi = uh2(fv.w);
            float t2, s2, fx;
            uint4 o;
            #define MIX(av, bb, ff) (t2 = fast_tanh((av) + (bb)), s2 = 1.0f - t2 * t2, \
                                     fx = (ff), 0.5f * (fx * s2) + 0.5f * fast_tanh(fx))
            o.x = h2u(MIX(acc[mt][2*j][0], bA.x, flo.x), MIX(acc[mt][2*j][1], bA.y, flo.y));
            o.y = h2u(MIX(acc[mt][2*j][2], bA.x, fhi.x), MIX(acc[mt][2*j][3], bA.y, fhi.y));
            o.z = h2u(MIX(acc[mt][2*j+1][0], bB.x, glo.x), MIX(acc[mt][2*j+1][1], bB.y, glo.y));
            o.w = h2u(MIX(acc[mt][2*j+1][2], bB.x, ghi.x), MIX(acc[mt][2*j+1][3], bB.y, ghi.y));
            #undef MIX
            *p = o;
        }
    }
    __syncthreads();

    // ---- GEMM3: f2 = g @ fW2^T ----
    ZERO_ACC(acc);
    gemm_ring(sb4, smx, ringb, g_wpk + 32768, wrow, wcol, lane, t, acc);

    // ---- epi3: h = .5*f2*s1 + .5*tanh(f2), s1 = 1 - t1^2 (t1 from SA, overwrite with h) ----
#pragma unroll
    for (int mt = 0; mt < 2; ++mt) {
        const int strip = wrow * 2 + mt;
#pragma unroll
        for (int j = 0; j < 4; ++j) {
            const int kkc = wcol * 4 + j;
            const int c0 = (wcol << 6) + (j << 4) + 2 * fc;
            uint4* p = sa4 + (strip * 16 + kkc) * 32 + lane;
            uint4 tv = *p;
            float2 bA = *(const float2*)(smF + O_FB2 / 4 + c0);
            float2 bB = *(const float2*)(smF + O_FB2 / 4 + c0 + 8);
            float2 tlo = uh2(tv.x), thi = uh2(tv.y), ulo = uh2(tv.z), uhi = uh2(tv.w);
            float f2, s1;
            uint4 o;
            #define HMX(av, bb, tt) (f2 = (av) + (bb), s1 = 1.0f - (tt) * (tt), \
                                     0.5f * (f2 * s1) + 0.5f * fast_tanh(f2))
            o.x = h2u(HMX(acc[mt][2*j][0], bA.x, tlo.x), HMX(acc[mt][2*j][1], bA.y, tlo.y));
            o.y = h2u(HMX(acc[mt][2*j][2], bA.x, thi.x), HMX(acc[mt][2*j][3], bA.y, thi.y));
            o.z = h2u(HMX(acc[mt][2*j+1][0], bB.x, ulo.x), HMX(acc[mt][2*j+1][1], bB.y, ulo.y));
            o.w = h2u(HMX(acc[mt][2*j+1][2], bB.x, uhi.x), HMX(acc[mt][2*j+1][3], bB.y, uhi.y));
            #undef HMX
            *p = o;
        }
    }

    // prefetch GEMM4 B frags (L2) before the barrier — acc is dead here
    uint2 B4[16];
    {
        const int nf4 = w & 1;
#pragma unroll
        for (int kk = 0; kk < 16; ++kk)
            B4[kk] = *(const uint2*)(g_wpk + 65536 + (((kk * 2 + nf4) * 32 + lane) * 2));
    }
    __syncthreads();

    // ---- GEMM4: o = h @ fW3^T ; symplectic swap -> out ----
    {
        const int strip = w >> 1, nf4 = w & 1;
        float o[4] = {0.0f, 0.0f, 0.0f, 0.0f};
#pragma unroll
        for (int kk = 0; kk < 16; ++kk) {
            uint4 A = sa4[(strip * 16 + kk) * 32 + lane];
            mma16816(o, A.x, A.y, A.z, A.w, B4[kk].x, B4[kk].y);
        }
        const int j0 = nf4 * 8 + 2 * fc;
        const int dst = (j0 + 8) & 15;
        const float sgn = (j0 < 8) ? -1.0f : 1.0f;
        const float b0 = smF[O_FB3 / 4 + j0], b1 = smF[O_FB3 / 4 + j0 + 1];
        const long rlo = n0 + strip * 16 + fr;
        *(float2*)(out + rlo * 16 + dst)       = make_float2(sgn * (o[0] + b0), sgn * (o[1] + b1));
        *(float2*)(out + (rlo + 8) * 16 + dst) = make_float2(sgn * (o[2] + b0), sgn * (o[3] + b1));
    }
}

extern "C" void kernel_launch(void* const* d_in, const int* in_sizes, int n_in,
                              void* d_out, int out_size)
{
    // metadata order: t, z, hW1, hb1, hW2, hb2, fW1, fb1, fW2, fb2, fW3, fb3
    const float* z   = (const float*)d_in[1];
    const float* hW1 = (const float*)d_in[2];
    const float* hb1 = (const float*)d_in[3];
    const float* hW2 = (const float*)d_in[4];
    const float* hb2 = (const float*)d_in[5];
    const float* fW1 = (const float*)d_in[6];
    const float* fb1 = (const float*)d_in[7];
    const float* fW2 = (const float*)d_in[8];
    const float* fb2 = (const float*)d_in[9];
    const float* fW3 = (const float*)d_in[10];
    const float* fb3 = (const float*)d_in[11];
    float* out = (float*)d_out;

    const int n = in_sizes[1] / 16;          // 131072 rows
    const int grid = n / BM;                 // 2048 CTAs

    prepack<<<140, 512>>>(hW2, fW2, fW3, hW1, fW1);

    cudaFuncSetAttribute(flexhnn_f16,
                         cudaFuncAttributeMaxDynamicSharedMemorySize, SMEMB);
    flexhnn_f16<<<grid, NT, SMEMB>>>(z, hb1, hb2, fb1, fb2, fb3, out);
}

// round 14
// speedup vs baseline: 1.0254x; 1.0254x over previous
#include <cuda_runtime.h>
#include <cuda_fp16.h>
#include <cstdint>

#define NT 256
#define BM 64

// fp16 fragment-packed weights, written by prepack:
// [0,32768)     hW2 frags, uint4-paired: ((kk*16+np)*32+lane)*4 + wd,
//               wd: nt=2np+(wd>>1), br=wd&1
// [32768,65536) fW2 frags (same layout)
// [65536,67584) fW3 frags: ((kk*2+nf)*32+lane)*2+br
// [67584,69632) hW1 frags: (nf*32+lane)*2+br   (K=16, single kk)
// [69632,71680) fW1 frags
__device__ __align__(16) uint32_t g_wpk[71680];

// ---- smem byte offsets ----
#define O_SA   0u        // 32KB: t1 frags (kept for s1 in epi3)
#define O_SB   32768u    // 32KB: f frags -> g frags
#define O_RING 65536u    // 4 x 8KB cp.async ring; reused as GEMM4 reduction pad
#define O_HB1  98304u    // f32[256]
#define O_FB1  99328u
#define O_HB2  100352u
#define O_FB2  101376u
#define O_FB3  102400u   // f32[16]
#define SMEMB  102464

#define CP_ASYNC16(d, s) \
    asm volatile("cp.async.cg.shared.global [%0], [%1], 16;" :: "r"(d), "l"(s))
#define CP_COMMIT() asm volatile("cp.async.commit_group;" ::: "memory")
#define CP_WAIT2()  asm volatile("cp.async.wait_group 2;" ::: "memory")
// pair barrier: the 64 threads (2 warps) that both stage and read one B quarter
#define PAIR_BAR(id) asm volatile("bar.sync %0, 64;" :: "r"(id) : "memory")

__device__ __forceinline__ uint32_t smem_u32(const void* p) {
    uint32_t a;
    asm("{ .reg .u64 t; cvta.to.shared.u64 t, %1; cvt.u32.u64 %0, t; }" : "=r"(a) : "l"(p));
    return a;
}
// hardware tanh: 1 MUFU op
__device__ __forceinline__ float fast_tanh(float x) {
    float y;
    asm("tanh.approx.f32 %0, %1;" : "=f"(y) : "f"(x));
    return y;
}
__device__ __forceinline__ uint32_t h2u(float lo, float hi) {
    uint32_t r;
    asm("{ .reg .b16 l, h; cvt.rn.f16.f32 l, %1; cvt.rn.f16.f32 h, %2; mov.b32 %0, {l, h}; }"
        : "=r"(r) : "f"(lo), "f"(hi));
    return r;
}
__device__ __forceinline__ float2 uh2(uint32_t u) {
    __half2 h = *(__half2*)&u;
    return __half22float2(h);
}
__device__ __forceinline__ void mma16816(float d[4],
    uint32_t a0, uint32_t a1, uint32_t a2, uint32_t a3, uint32_t b0, uint32_t b1) {
    asm volatile("mma.sync.aligned.m16n8k16.row.col.f32.f16.f16.f32 "
                 "{%0,%1,%2,%3},{%4,%5,%6,%7},{%8,%9},{%0,%1,%2,%3};"
                 : "+f"(d[0]), "+f"(d[1]), "+f"(d[2]), "+f"(d[3])
                 : "r"(a0), "r"(a1), "r"(a2), "r"(a3), "r"(b0), "r"(b1));
}

// ---------- prepack ----------
__global__ void __launch_bounds__(512) prepack(const float* __restrict__ hW2,
                                               const float* __restrict__ fW2,
                                               const float* __restrict__ fW3,
                                               const float* __restrict__ hW1,
                                               const float* __restrict__ fW1) {
    int tid = blockIdx.x * 512 + threadIdx.x;
    if (tid < 65536) {
        int off = tid & 32767;
        const float* W = (tid >> 15) ? fW2 : hW2;
        // uint4-paired layout: wd selects (nt parity, br)
        int wd = off & 3, lane = (off >> 2) & 31, np = (off >> 7) & 15, kk = off >> 11;
        int nt = 2 * np + (wd >> 1), br = wd & 1;
        int n = nt * 8 + (lane >> 2), k = kk * 16 + 2 * (lane & 3) + br * 8;
        g_wpk[tid] = h2u(W[n * 256 + k], W[n * 256 + k + 1]);
    } else if (tid < 67584) {
        int off = tid - 65536;
        int br = off & 1, lane = (off >> 1) & 31, nf = (off >> 6) & 1, kk = off >> 7;
        int n = nf * 8 + (lane >> 2), k = kk * 16 + 2 * (lane & 3) + br * 8;
        g_wpk[tid] = h2u(fW3[n * 256 + k], fW3[n * 256 + k + 1]);
    } else if (tid < 71680) {
        int off = tid - 67584;
        const float* W = (off >= 2048) ? fW1 : hW1;
        off &= 2047;
        int br = off & 1, lane = (off >> 1) & 31, nf = off >> 6;
        int n = nf * 8 + (lane >> 2), k = 2 * (lane & 3) + br * 8;
        g_wpk[tid] = h2u(W[n * 16 + k], W[n * 16 + k + 1]);
    }
}

// PAIR-LOCAL staging (R10-proven): thread t writes bytes [t*32, t*32+32), so
// pair q (threads 64q..64q+63) stages exactly its own B-quarter [2048q, 2048(q+1))
// of each chunk. This invariant is what makes pair-only barriers correct —
// do NOT change the addressing (R12's t*16 split broke it and corrupted GEMM3 B).
__device__ __forceinline__ void ring_issue(uint32_t ringb, const uint32_t* wsrc, int c, int t) {
    if (c < 16) {
        uint32_t dst = ringb + (uint32_t)(((c & 3) << 13) + (t << 5));
        const char* src = (const char*)(wsrc + (c << 11)) + (t << 5);
        CP_ASYNC16(dst, src);
        CP_ASYNC16(dst + 16, src + 16);
    }
    CP_COMMIT();
}

#define ZERO_ACC(acc) do { \
    _Pragma("unroll") for (int _m = 0; _m < 2; ++_m) \
    _Pragma("unroll") for (int _n = 0; _n < 8; ++_n) \
    _Pragma("unroll") for (int _i = 0; _i < 4; ++_i) (acc)[_m][_n][_i] = 0.0f; \
} while (0)

// Big GEMM: A frags from ab (smem), B streamed from wsrc via ring.
// Pair barriers only; A register double-buffered; cp.async in B-LDS shadow.
// Prologue (chunks 0..2) must already be issued. Ends with a pair barrier.
__device__ __forceinline__ void gemm_ring(const uint4* __restrict__ ab, const char* smx,
                                          uint32_t ringb, const uint32_t* __restrict__ wsrc,
                                          int wrow, int wcol, int lane, int t,
                                          float acc[2][8][4]) {
    const int s0 = wrow * 2;
    const int bid = 1 + wcol;
    uint4 A0 = ab[(s0 * 16) * 32 + lane];          // preload kk=0 (post caller-sync)
    uint4 A1 = ab[((s0 + 1) * 16) * 32 + lane];
#pragma unroll
    for (int kk = 0; kk < 16; ++kk) {
        CP_WAIT2();
        PAIR_BAR(bid);
        const uint4* rb4 = (const uint4*)(smx + O_RING + ((kk & 3) << 13));
        uint4 B[4];
#pragma unroll
        for (int j = 0; j < 4; ++j)
            B[j] = rb4[((wcol << 2) + j) * 32 + lane];
        ring_issue(ringb, wsrc, kk + 3, t);        // in B-LDS shadow
        uint4 C0 = A0, C1 = A1;
        if (kk < 15) {                             // prefetch next-kk A during MMAs
            A0 = ab[(s0 * 16 + kk + 1) * 32 + lane];
            A1 = ab[((s0 + 1) * 16 + kk + 1) * 32 + lane];
        }
#pragma unroll
        for (int j = 0; j < 4; ++j) {
            mma16816(acc[0][2*j],   C0.x, C0.y, C0.z, C0.w, B[j].x, B[j].y);
            mma16816(acc[1][2*j],   C1.x, C1.y, C1.z, C1.w, B[j].x, B[j].y);
            mma16816(acc[0][2*j+1], C0.x, C0.y, C0.z, C0.w, B[j].z, B[j].w);
            mma16816(acc[1][2*j+1], C1.x, C1.y, C1.z, C1.w, B[j].z, B[j].w);
        }
    }
    PAIR_BAR(bid);   // pair's ring reads done before slots reused by next prologue
}

__global__ void __launch_bounds__(NT, 2)
flexhnn_f16(const float* __restrict__ z,
            const float* __restrict__ hb1, const float* __restrict__ hb2,
            const float* __restrict__ fb1, const float* __restrict__ fb2,
            const float* __restrict__ fb3,
            float* __restrict__ out)
{
    extern __shared__ __align__(16) char smx[];
    float* smF = (float*)smx;
    uint4* sa4 = (uint4*)(smx + O_SA);
    uint4* sb4 = (uint4*)(smx + O_SB);
    const uint32_t ringb = smem_u32(smx) + O_RING;

    const int t = threadIdx.x, lane = t & 31, w = t >> 5;
    const int fr = lane >> 2, fc = lane & 3;
    const int wrow = w & 1, wcol = w >> 1;     // 8 warps: 2 row-halves x 4 col-quarters
    const long n0 = (long)blockIdx.x * BM;

    // ---- early prefetch: GEMM1a B frags (hW1) — hides L2 latency behind staging ----
    uint2 B1[8];
#pragma unroll
    for (int nt = 0; nt < 8; ++nt)
        B1[nt] = *(const uint2*)(g_wpk + 67584 + (((wcol << 3) + nt) * 32 + lane) * 2);

    // ---- GEMM1: z A-frags (fp16) ----
    uint4 Az[2];
#pragma unroll
    for (int mt = 0; mt < 2; ++mt) {
        const long rl = n0 + (wrow * 32 + mt * 16 + fr);
        float2 zl0 = *(const float2*)(z + rl * 16 + 2 * fc);
        float2 zl8 = *(const float2*)(z + rl * 16 + 2 * fc + 8);
        float2 zh0 = *(const float2*)(z + (rl + 8) * 16 + 2 * fc);
        float2 zh8 = *(const float2*)(z + (rl + 8) * 16 + 2 * fc + 8);
        Az[mt].x = h2u(zl0.x, zl0.y); Az[mt].y = h2u(zh0.x, zh0.y);
        Az[mt].z = h2u(zl8.x, zl8.y); Az[mt].w = h2u(zh8.x, zh8.y);
    }

    // ---- stage biases ----
    smF[O_HB1 / 4 + t] = hb1[t];
    smF[O_FB1 / 4 + t] = fb1[t];
    smF[O_HB2 / 4 + t] = hb2[t];
    smF[O_FB2 / 4 + t] = fb2[t];
    if (t < 16) smF[O_FB3 / 4 + t] = fb3[t];
    __syncthreads();

    float acc[2][8][4];

    // ---- GEMM1a: a1 = z @ hW1^T ; epi1a: t1 -> SA frags ----
    ZERO_ACC(acc);
#pragma unroll
    for (int nt = 0; nt < 8; ++nt) {
        mma16816(acc[0][nt], Az[0].x, Az[0].y, Az[0].z, Az[0].w, B1[nt].x, B1[nt].y);
        mma16816(acc[1][nt], Az[1].x, Az[1].y, Az[1].z, Az[1].w, B1[nt].x, B1[nt].y);
    }
    // prefetch GEMM1b B frags (fW1) during epi1a
#pragma unroll
    for (int nt = 0; nt < 8; ++nt)
        B1[nt] = *(const uint2*)(g_wpk + 69632 + (((wcol << 3) + nt) * 32 + lane) * 2);
#pragma unroll
    for (int mt = 0; mt < 2; ++mt) {
        const int strip = wrow * 2 + mt;
#pragma unroll
        for (int j = 0; j < 4; ++j) {
            const int kkc = wcol * 4 + j;
            const int c0 = (wcol << 6) + (j << 4) + 2 * fc;
            float2 bA = *(const float2*)(smF + O_HB1 / 4 + c0);
            float2 bB = *(const float2*)(smF + O_HB1 / 4 + c0 + 8);
            uint4 v;
            v.x = h2u(fast_tanh(acc[mt][2*j][0] + bA.x), fast_tanh(acc[mt][2*j][1] + bA.y));
            v.y = h2u(fast_tanh(acc[mt][2*j][2] + bA.x), fast_tanh(acc[mt][2*j][3] + bA.y));
            v.z = h2u(fast_tanh(acc[mt][2*j+1][0] + bB.x), fast_tanh(acc[mt][2*j+1][1] + bB.y));
            v.w = h2u(fast_tanh(acc[mt][2*j+1][2] + bB.x), fast_tanh(acc[mt][2*j+1][3] + bB.y));
            sa4[(strip * 16 + kkc) * 32 + lane] = v;
        }
    }

    // ---- GEMM1b: f = z @ fW1^T + fb1 ; epi1b: f -> SB frags ----
    ZERO_ACC(acc);
#pragma unroll
    for (int nt = 0; nt < 8; ++nt) {
        mma16816(acc[0][nt], Az[0].x, Az[0].y, Az[0].z, Az[0].w, B1[nt].x, B1[nt].y);
        mma16816(acc[1][nt], Az[1].x, Az[1].y, Az[1].z, Az[1].w, B1[nt].x, B1[nt].y);
    }
#pragma unroll
    for (int mt = 0; mt < 2; ++mt) {
        const int strip = wrow * 2 + mt;
#pragma unroll
        for (int j = 0; j < 4; ++j) {
            const int kkc = wcol * 4 + j;
            const int c0 = (wcol << 6) + (j << 4) + 2 * fc;
            float2 bA = *(const float2*)(smF + O_FB1 / 4 + c0);
            float2 bB = *(const float2*)(smF + O_FB1 / 4 + c0 + 8);
            uint4 v;
            v.x = h2u(acc[mt][2*j][0] + bA.x, acc[mt][2*j][1] + bA.y);
            v.y = h2u(acc[mt][2*j][2] + bA.x, acc[mt][2*j][3] + bA.y);
            v.z = h2u(acc[mt][2*j+1][0] + bB.x, acc[mt][2*j+1][1] + bB.y);
            v.w = h2u(acc[mt][2*j+1][2] + bB.x, acc[mt][2*j+1][3] + bB.y);
            sb4[(strip * 16 + kkc) * 32 + lane] = v;
        }
    }

    // prologue for GEMM2 ring (hW2), then make SA/SB visible
    ring_issue(ringb, g_wpk, 0, t);
    ring_issue(ringb, g_wpk, 1, t);
    ring_issue(ringb, g_wpk, 2, t);
    __syncthreads();

    // ---- GEMM2: a2 = t1 @ hW2^T ----
    ZERO_ACC(acc);
    gemm_ring(sa4, smx, ringb, g_wpk, wrow, wcol, lane, t, acc);

    // prologue for GEMM3 ring (fW2) — pair-local staging makes this safe post-PAIR_BAR
    ring_issue(ringb, g_wpk + 32768, 0, t);
    ring_issue(ringb, g_wpk + 32768, 1, t);
    ring_issue(ringb, g_wpk + 32768, 2, t);

    // ---- epi2: g = .5*f*s2 + .5*tanh(f)  (f from SB, overwrite with g) ----
#pragma unroll
    for (int mt = 0; mt < 2; ++mt) {
        const int strip = wrow * 2 + mt;
#pragma unroll
        for (int j = 0; j < 4; ++j) {
            const int kkc = wcol * 4 + j;
            const int c0 = (wcol << 6) + (j << 4) + 2 * fc;
            uint4* p = sb4 + (strip * 16 + kkc) * 32 + lane;
            uint4 fv = *p;
            float2 bA = *(const float2*)(smF + O_HB2 / 4 + c0);
            float2 bB = *(const float2*)(smF + O_HB2 / 4 + c0 + 8);
            float2 flo = uh2(fv.x), fhi = uh2(fv.y), glo = uh2(fv.z), ghi = uh2(fv.w);
            float t2, s2, fx;
            uint4 o;
            #define MIX(av, bb, ff) (t2 = fast_tanh((av) + (bb)), s2 = 1.0f - t2 * t2, \
                                     fx = (ff), 0.5f * (fx * s2) + 0.5f * fast_tanh(fx))
            o.x = h2u(MIX(acc[mt][2*j][0], bA.x, flo.x), MIX(acc[mt][2*j][1], bA.y, flo.y));
            o.y = h2u(MIX(acc[mt][2*j][2], bA.x, fhi.x), MIX(acc[mt][2*j][3], bA.y, fhi.y));
            o.z = h2u(MIX(acc[mt][2*j+1][0], bB.x, glo.x), MIX(acc[mt][2*j+1][1], bB.y, glo.y));
            o.w = h2u(MIX(acc[mt][2*j+1][2], bB.x, ghi.x), MIX(acc[mt][2*j+1][3], bB.y, ghi.y));
            #undef MIX
            *p = o;
        }
    }
    __syncthreads();

    // ---- GEMM3: f2 = g @ fW2^T ----
    ZERO_ACC(acc);
    gemm_ring(sb4, smx, ringb, g_wpk + 32768, wrow, wcol, lane, t, acc);
    __syncthreads();   // ALL pairs' ring reads done before pad overwrites ring

    // ---- GEMM4 B frags for this warp's kkc quarter (L2) ----
    uint2 B4[4][2];
#pragma unroll
    for (int j = 0; j < 4; ++j)
#pragma unroll
        for (int nf = 0; nf < 2; ++nf)
            B4[j][nf] = *(const uint2*)(g_wpk + 65536 +
                            ((((wcol * 4 + j) * 2 + nf) * 32 + lane) * 2));

    // ---- epi3 fused with GEMM4 partials: h never touches smem ----
    float o4[2][2][4];
#pragma unroll
    for (int mt = 0; mt < 2; ++mt)
#pragma unroll
        for (int nf = 0; nf < 2; ++nf)
#pragma unroll
            for (int i = 0; i < 4; ++i) o4[mt][nf][i] = 0.0f;

#pragma unroll
    for (int mt = 0; mt < 2; ++mt) {
        const int strip = wrow * 2 + mt;
#pragma unroll
        for (int j = 0; j < 4; ++j) {
            const int kkc = wcol * 4 + j;
            const int c0 = (wcol << 6) + (j << 4) + 2 * fc;
            uint4 tv = sa4[(strip * 16 + kkc) * 32 + lane];
            float2 bA = *(const float2*)(smF + O_FB2 / 4 + c0);
            float2 bB = *(const float2*)(smF + O_FB2 / 4 + c0 + 8);
            float2 tlo = uh2(tv.x), thi = uh2(tv.y), ulo = uh2(tv.z), uhi = uh2(tv.w);
            float f2, s1;
            uint4 v;
            #define HMX(av, bb, tt) (f2 = (av) + (bb), s1 = 1.0f - (tt) * (tt), \
                                     0.5f * (f2 * s1) + 0.5f * fast_tanh(f2))
            v.x = h2u(HMX(acc[mt][2*j][0], bA.x, tlo.x), HMX(acc[mt][2*j][1], bA.y, tlo.y));
            v.y = h2u(HMX(acc[mt][2*j][2], bA.x, thi.x), HMX(acc[mt][2*j][3], bA.y, thi.y));
            v.z = h2u(HMX(acc[mt][2*j+1][0], bB.x, ulo.x), HMX(acc[mt][2*j+1][1], bB.y, ulo.y));
            v.w = h2u(HMX(acc[mt][2*j+1][2], bB.x, uhi.x), HMX(acc[mt][2*j+1][3], bB.y, uhi.y));
            #undef HMX
            mma16816(o4[mt][0], v.x, v.y, v.z, v.w, B4[j][0].x, B4[j][0].y);
            mma16816(o4[mt][1], v.x, v.y, v.z, v.w, B4[j][1].x, B4[j][1].y);
        }
    }

    // ---- write K-quarter partials to reduction pad (ring smem is dead now) ----
    {
        float* red = (float*)(smx + O_RING);
#pragma unroll
        for (int mt = 0; mt < 2; ++mt)
#pragma unroll
            for (int nf = 0; nf < 2; ++nf) {
                int chunk = (wrow * 2 + mt) * 2 + nf;
                *(float4*)(red + (chunk * 4 + wcol) * 128 + lane * 4) =
                    make_float4(o4[mt][nf][0], o4[mt][nf][1], o4[mt][nf][2], o4[mt][nf][3]);
            }
    }
    __syncthreads();

    // ---- reduce across wcol quarters ; bias ; symplectic swap -> out ----
    {
        const float* red = (const float*)(smx + O_RING);
        const int strip = w >> 1, nf4 = w & 1;       // chunk == w
        float4 r0 = *(const float4*)(red + (w * 4 + 0) * 128 + lane * 4);
        float4 r1 = *(const float4*)(red + (w * 4 + 1) * 128 + lane * 4);
        float4 r2 = *(const float4*)(red + (w * 4 + 2) * 128 + lane * 4);
        float4 r3 = *(const float4*)(red + (w * 4 + 3) * 128 + lane * 4);
        float o[4] = { r0.x + r1.x + r2.x + r3.x,
                       r0.y + r1.y + r2.y + r3.y,
                       r0.z + r1.z + r2.z + r3.z,
                       r0.w + r1.w + r2.w + r3.w };
        const int j0 = nf4 * 8 + 2 * fc;
        const int dst = (j0 + 8) & 15;
        const float sgn = (j0 < 8) ? -1.0f : 1.0f;
        const float b0 = smF[O_FB3 / 4 + j0], b1 = smF[O_FB3 / 4 + j0 + 1];
        const long rlo = n0 + strip * 16 + fr;
        *(float2*)(out + rlo * 16 + dst)       = make_float2(sgn * (o[0] + b0), sgn * (o[1] + b1));
        *(float2*)(out + (rlo + 8) * 16 + dst) = make_float2(sgn * (o[2] + b0), sgn * (o[3] + b1));
    }
}

extern "C" void kernel_launch(void* const* d_in, const int* in_sizes, int n_in,
                              void* d_out, int out_size)
{
    // metadata order: t, z, hW1, hb1, hW2, hb2, fW1, fb1, fW2, fb2, fW3, fb3
    const float* z   = (const float*)d_in[1];
    const float* hW1 = (const float*)d_in[2];
    const float* hb1 = (const float*)d_in[3];
    const float* hW2 = (const float*)d_in[4];
    const float* hb2 = (const float*)d_in[5];
    const float* fW1 = (const float*)d_in[6];
    const float* fb1 = (const float*)d_in[7];
    const float* fW2 = (const float*)d_in[8];
    const float* fb2 = (const float*)d_in[9];
    const float* fW3 = (const float*)d_in[10];
    const float* fb3 = (const float*)d_in[11];
    float* out = (float*)d_out;

    const int n = in_sizes[1] / 16;          // 131072 rows
    const int grid = n / BM;                 // 2048 CTAs

    prepack<<<140, 512>>>(hW2, fW2, fW3, hW1, fW1);

    cudaFuncSetAttribute(flexhnn_f16,
                         cudaFuncAttributeMaxDynamicSharedMemorySize, SMEMB);
    flexhnn_f16<<<grid, NT, SMEMB>>>(z, hb1, hb2, fb1, fb2, fb3, out);
}